// round 1
// baseline (speedup 1.0000x reference)
#include <cuda_runtime.h>
#include <cuda_bf16.h>
#include <cstdint>

// Problem constants (fixed by setup_inputs)
#define B_   2
#define T_   2048
#define C_   2048
#define H_   16
#define DH_  128
#define M_   (B_ * T_)   // 4096

// Scratch (device globals — allocation-free per harness rules)
__device__ float g_Q[(size_t)M_ * C_];   // 32 MB: x @ Wq, layout [b*t, h*128+d]
__device__ float g_K[(size_t)M_ * DH_];  //  2 MB: x @ Wk
__device__ float g_V[(size_t)M_ * DH_];  //  2 MB: x @ Wv
__device__ float g_Y[(size_t)M_ * C_];   // 32 MB: attention output, [b*t, h*128+d]

// ---------------------------------------------------------------------------
// Generic fp32 tiled GEMM: C[M,N] = A[M,K] @ B[K,N], all row-major.
// 256 threads. Thread grid (BN/TN) x (BM/TM) must be 16x16.
// Strided register mapping: rows = ty + i*16, cols = tx + j*16 (conflict-free LDS).
// ---------------------------------------------------------------------------
template<int BM, int BN, int BK, int TM, int TN>
__global__ __launch_bounds__(256) void gemm_f32(
    const float* __restrict__ A, const float* __restrict__ B,
    float* __restrict__ C, int M, int N, int K)
{
    __shared__ float As[BK][BM + 1];  // +1 pad: conflict-free transposed store
    __shared__ float Bs[BK][BN];

    const int tid = threadIdx.x;
    const int tx  = tid & 15;   // BN/TN == 16
    const int ty  = tid >> 4;   // BM/TM == 16

    const int rowBase = blockIdx.y * BM;
    const int colBase = blockIdx.x * BN;

    float acc[TM][TN];
    #pragma unroll
    for (int i = 0; i < TM; i++)
        #pragma unroll
        for (int j = 0; j < TN; j++) acc[i][j] = 0.0f;

    for (int k0 = 0; k0 < K; k0 += BK) {
        // Load A tile (transposed into As[c][r])
        #pragma unroll
        for (int i = tid; i < BM * BK; i += 256) {
            int r = i / BK, c = i % BK;
            As[c][r] = A[(size_t)(rowBase + r) * K + k0 + c];
        }
        // Load B tile
        #pragma unroll
        for (int i = tid; i < BK * BN; i += 256) {
            int r = i / BN, c = i % BN;
            Bs[r][c] = B[(size_t)(k0 + r) * N + colBase + c];
        }
        __syncthreads();

        #pragma unroll
        for (int k = 0; k < BK; k++) {
            float ra[TM], rb[TN];
            #pragma unroll
            for (int i = 0; i < TM; i++) ra[i] = As[k][ty + i * 16];
            #pragma unroll
            for (int j = 0; j < TN; j++) rb[j] = Bs[k][tx + j * 16];
            #pragma unroll
            for (int i = 0; i < TM; i++)
                #pragma unroll
                for (int j = 0; j < TN; j++)
                    acc[i][j] += ra[i] * rb[j];
        }
        __syncthreads();
    }

    #pragma unroll
    for (int i = 0; i < TM; i++) {
        int row = rowBase + ty + i * 16;
        #pragma unroll
        for (int j = 0; j < TN; j++) {
            C[(size_t)row * N + colBase + tx + j * 16] = acc[i][j];
        }
    }
}

// ---------------------------------------------------------------------------
// Flash attention for MQA (single shared KV head).
// Tq=64 query rows per CTA, Tk=64 keys per tile, d=128.
// 256 threads: tx=tid&15 (S cols), ty=tid>>4 (S rows: ty*4..ty*4+3).
// Grid: (T/64, H, B).
// Q layout: [b*T + t, h*128 + d]; K,V: [b*T + s, d]; Y out: [b*T + t, h*128 + d].
// ---------------------------------------------------------------------------
__global__ __launch_bounds__(256) void flash_mqa(
    const float* __restrict__ Q, const float* __restrict__ K,
    const float* __restrict__ V, float* __restrict__ Y)
{
    const int qt  = blockIdx.x;
    const int h   = blockIdx.y;
    const int b   = blockIdx.z;
    const int tid = threadIdx.x;
    const int tx  = tid & 15;
    const int ty  = tid >> 4;
    const int q0  = qt * 64;
    const float scale = 0.08838834764831845f;  // 128^-0.5

    // Qs/Ks alias the same region as Vs (never live simultaneously)
    __shared__ float sU[2 * 32 * 65];         // 16.25 KB
    float (*Qs)[65]  = (float(*)[65])sU;
    float (*Ks)[65]  = (float(*)[65])(sU + 32 * 65);
    float (*Vs)[128] = (float(*)[128])sU;
    __shared__ float Ps[64][65];              // 16.25 KB (padded)

    float o[4][8];
    float m[4], l[4];
    #pragma unroll
    for (int i = 0; i < 4; i++) {
        m[i] = -1e30f; l[i] = 0.0f;
        #pragma unroll
        for (int j = 0; j < 8; j++) o[i][j] = 0.0f;
    }

    const float* Qbase = Q + ((size_t)b * T_ + q0) * C_ + h * DH_;
    const float* Kbase = K + (size_t)b * T_ * DH_;
    const float* Vbase = V + (size_t)b * T_ * DH_;

    for (int s0 = 0; s0 < T_; s0 += 64) {
        // ---- S = scale * Q @ K^T  (64x64), accumulated over d in chunks of 32
        float s[4][4];
        #pragma unroll
        for (int i = 0; i < 4; i++)
            #pragma unroll
            for (int j = 0; j < 4; j++) s[i][j] = 0.0f;

        for (int dk = 0; dk < DH_; dk += 32) {
            __syncthreads();  // prior phase finished with smem
            #pragma unroll
            for (int i2 = tid; i2 < 64 * 32; i2 += 256) {
                int r = i2 >> 5, c = i2 & 31;
                Qs[c][r] = Qbase[(size_t)r * C_ + dk + c] * scale;
                Ks[c][r] = Kbase[(size_t)(s0 + r) * DH_ + dk + c];
            }
            __syncthreads();
            #pragma unroll
            for (int c = 0; c < 32; c++) {
                float ra[4], rb[4];
                #pragma unroll
                for (int i = 0; i < 4; i++) ra[i] = Qs[c][ty * 4 + i];
                #pragma unroll
                for (int j = 0; j < 4; j++) rb[j] = Ks[c][tx + 16 * j];
                #pragma unroll
                for (int i = 0; i < 4; i++)
                    #pragma unroll
                    for (int j = 0; j < 4; j++)
                        s[i][j] += ra[i] * rb[j];
            }
        }

        // ---- online softmax (row stats replicated across the 16 tx lanes)
        #pragma unroll
        for (int i = 0; i < 4; i++) {
            float mx = fmaxf(fmaxf(s[i][0], s[i][1]), fmaxf(s[i][2], s[i][3]));
            mx = fmaxf(mx, __shfl_xor_sync(0xffffffffu, mx, 8));
            mx = fmaxf(mx, __shfl_xor_sync(0xffffffffu, mx, 4));
            mx = fmaxf(mx, __shfl_xor_sync(0xffffffffu, mx, 2));
            mx = fmaxf(mx, __shfl_xor_sync(0xffffffffu, mx, 1));
            float mnew  = fmaxf(m[i], mx);
            float alpha = __expf(m[i] - mnew);
            float rs = 0.0f;
            #pragma unroll
            for (int j = 0; j < 4; j++) {
                s[i][j] = __expf(s[i][j] - mnew);
                rs += s[i][j];
            }
            rs += __shfl_xor_sync(0xffffffffu, rs, 8);
            rs += __shfl_xor_sync(0xffffffffu, rs, 4);
            rs += __shfl_xor_sync(0xffffffffu, rs, 2);
            rs += __shfl_xor_sync(0xffffffffu, rs, 1);
            l[i] = l[i] * alpha + rs;
            m[i] = mnew;
            #pragma unroll
            for (int jj = 0; jj < 8; jj++) o[i][jj] *= alpha;
        }

        // ---- publish P
        #pragma unroll
        for (int i = 0; i < 4; i++)
            #pragma unroll
            for (int j = 0; j < 4; j++)
                Ps[ty * 4 + i][tx + 16 * j] = s[i][j];
        __syncthreads();  // Ps visible; all S-phase Qs/Ks reads done

        // ---- O += P @ V, V streamed in 32-key chunks (Vs aliases Qs/Ks)
        for (int vk = 0; vk < 64; vk += 32) {
            #pragma unroll
            for (int i2 = tid; i2 < 32 * 128; i2 += 256) {
                int kr = i2 >> 7, d = i2 & 127;
                Vs[kr][d] = Vbase[(size_t)(s0 + vk + kr) * DH_ + d];
            }
            __syncthreads();
            #pragma unroll
            for (int c = 0; c < 32; c++) {
                float rp[4], rv[8];
                #pragma unroll
                for (int i = 0; i < 4; i++)  rp[i]  = Ps[ty * 4 + i][vk + c];
                #pragma unroll
                for (int jj = 0; jj < 8; jj++) rv[jj] = Vs[c][tx + 16 * jj];
                #pragma unroll
                for (int i = 0; i < 4; i++)
                    #pragma unroll
                    for (int jj = 0; jj < 8; jj++)
                        o[i][jj] += rp[i] * rv[jj];
            }
            __syncthreads();
        }
    }

    // ---- normalize and write Y in [b*t, h*128 + d] layout
    #pragma unroll
    for (int i = 0; i < 4; i++) {
        float inv = 1.0f / l[i];
        size_t row = (size_t)b * T_ + q0 + ty * 4 + i;
        #pragma unroll
        for (int jj = 0; jj < 8; jj++)
            Y[row * C_ + h * DH_ + tx + 16 * jj] = o[i][jj] * inv;
    }
}

// ---------------------------------------------------------------------------
// Launch
// ---------------------------------------------------------------------------
extern "C" void kernel_launch(void* const* d_in, const int* in_sizes, int n_in,
                              void* d_out, int out_size)
{
    const float* x  = (const float*)d_in[0];
    const float* Wq = (const float*)d_in[1];
    const float* Wk = (const float*)d_in[2];
    const float* Wv = (const float*)d_in[3];
    const float* Wo = (const float*)d_in[4];
    float* out = (float*)d_out;

    float *Qp, *Kp, *Vp, *Yp;
    cudaGetSymbolAddress((void**)&Qp, g_Q);
    cudaGetSymbolAddress((void**)&Kp, g_K);
    cudaGetSymbolAddress((void**)&Vp, g_V);
    cudaGetSymbolAddress((void**)&Yp, g_Y);

    // 1) Q = x @ Wq   [4096,2048] = [4096,2048] @ [2048,2048]
    {
        dim3 grid(C_ / 128, M_ / 128);
        gemm_f32<128, 128, 16, 8, 8><<<grid, 256>>>(x, Wq, Qp, M_, C_, C_);
    }
    // 2) K = x @ Wk   [4096,128]
    {
        dim3 grid(DH_ / 128, M_ / 64);
        gemm_f32<64, 128, 16, 4, 8><<<grid, 256>>>(x, Wk, Kp, M_, DH_, C_);
    }
    // 3) V = x @ Wv
    {
        dim3 grid(DH_ / 128, M_ / 64);
        gemm_f32<64, 128, 16, 4, 8><<<grid, 256>>>(x, Wv, Vp, M_, DH_, C_);
    }
    // 4) Flash MQA attention -> Y
    {
        dim3 grid(T_ / 64, H_, B_);
        flash_mqa<<<grid, 256>>>(Qp, Kp, Vp, Yp);
    }
    // 5) out = Y @ Wo
    {
        dim3 grid(C_ / 128, M_ / 128);
        gemm_f32<128, 128, 16, 8, 8><<<grid, 256>>>(Yp, Wo, out, M_, C_, C_);
    }
}

// round 3
// speedup vs baseline: 1.6787x; 1.6787x over previous
#include <cuda_runtime.h>
#include <cuda_bf16.h>
#include <cstdint>

// Problem constants (fixed by setup_inputs)
#define B_   2
#define T_   2048
#define C_   2048
#define H_   16
#define DH_  128
#define M_   (B_ * T_)   // 4096

// Scratch (device globals — allocation-free per harness rules)
__device__ float g_Q[(size_t)M_ * C_];   // 32 MB
__device__ float g_K[(size_t)M_ * DH_];  //  2 MB
__device__ float g_V[(size_t)M_ * DH_];  //  2 MB
__device__ float g_Y[(size_t)M_ * C_];   // 32 MB

__device__ __forceinline__ float tf32r(float x) {
    float y;
    asm("cvt.rna.tf32.f32 %0, %1;" : "=f"(y) : "f"(x));
    return y;
}

__device__ __forceinline__ void mma_tf32(float* d, const uint32_t* a, const uint32_t* b) {
    asm volatile(
        "mma.sync.aligned.m16n8k8.row.col.f32.tf32.tf32.f32 "
        "{%0,%1,%2,%3}, {%4,%5,%6,%7}, {%8,%9}, {%0,%1,%2,%3};"
        : "+f"(d[0]), "+f"(d[1]), "+f"(d[2]), "+f"(d[3])
        : "r"(a[0]), "r"(a[1]), "r"(a[2]), "r"(a[3]), "r"(b[0]), "r"(b[1]));
}

// ---------------------------------------------------------------------------
// tf32 tensor-core GEMM via mma.sync (portable under compute_103):
//   C[Mr,Nc] = A[Mr,Kd] @ B[Kd,Nc]   (both row-major, fp32 in/out)
// CTA tile 128x128, BK=16, 8 warps (2x4), warp tile 64x32.
// Grid: (Nc/128, Mr/128). 256 threads.
// ---------------------------------------------------------------------------
#define AS_STRIDE 20    // As[m][k]: bank-conflict-free fragment loads
#define BS_STRIDE 136   // Bs[k][n]: bank-conflict-free fragment loads + stores

__global__ __launch_bounds__(256) void gemm_mma_tf32(
    const float* __restrict__ A, const float* __restrict__ B,
    float* __restrict__ Cc, int Mr, int Nc, int Kd)
{
    __shared__ float As[2][128 * AS_STRIDE];  // 20 KB
    __shared__ float Bs[2][16 * BS_STRIDE];   // 17 KB

    const int tid    = threadIdx.x;
    const int wid    = tid >> 5;
    const int lane   = tid & 31;
    const int g      = lane >> 2;   // group id (row within fragment)
    const int tq     = lane & 3;    // thread-in-group
    const int warp_m = wid & 1;     // 0..1
    const int warp_n = wid >> 1;    // 0..3
    const int rowBase = blockIdx.y * 128;
    const int colBase = blockIdx.x * 128;

    // Per-thread gmem staging: A 2 float4, B 2 float4 per chunk
    const int am = tid >> 2;            // 0..63  (row within tile, +64 on second)
    const int aq = tid & 3;             // float4 index within 16-float row chunk
    const int bk = tid >> 5;            // 0..7   (k row, +8 on second)
    const int bn = tid & 31;            // float4 index within 128-float n row

    float acc[4][4][4];
    #pragma unroll
    for (int mi = 0; mi < 4; mi++)
        #pragma unroll
        for (int ni = 0; ni < 4; ni++)
            #pragma unroll
            for (int r = 0; r < 4; r++) acc[mi][ni][r] = 0.0f;

    const int nK = Kd >> 4;  // chunks of 16

    float4 pa0, pa1, pb0, pb1;
    auto ldg_chunk = [&](int kc) {
        const float* Ab = A + (size_t)(rowBase) * Kd + kc * 16;
        const float* Bb = B + (size_t)(kc * 16) * Nc + colBase;
        pa0 = *reinterpret_cast<const float4*>(Ab + (size_t)am * Kd + aq * 4);
        pa1 = *reinterpret_cast<const float4*>(Ab + (size_t)(am + 64) * Kd + aq * 4);
        pb0 = *reinterpret_cast<const float4*>(Bb + (size_t)bk * Nc + bn * 4);
        pb1 = *reinterpret_cast<const float4*>(Bb + (size_t)(bk + 8) * Nc + bn * 4);
    };
    auto sts_chunk = [&](int s) {
        float4 va0 = make_float4(tf32r(pa0.x), tf32r(pa0.y), tf32r(pa0.z), tf32r(pa0.w));
        float4 va1 = make_float4(tf32r(pa1.x), tf32r(pa1.y), tf32r(pa1.z), tf32r(pa1.w));
        float4 vb0 = make_float4(tf32r(pb0.x), tf32r(pb0.y), tf32r(pb0.z), tf32r(pb0.w));
        float4 vb1 = make_float4(tf32r(pb1.x), tf32r(pb1.y), tf32r(pb1.z), tf32r(pb1.w));
        *reinterpret_cast<float4*>(&As[s][am * AS_STRIDE + aq * 4])        = va0;
        *reinterpret_cast<float4*>(&As[s][(am + 64) * AS_STRIDE + aq * 4]) = va1;
        *reinterpret_cast<float4*>(&Bs[s][bk * BS_STRIDE + bn * 4])        = vb0;
        *reinterpret_cast<float4*>(&Bs[s][(bk + 8) * BS_STRIDE + bn * 4])  = vb1;
    };

    ldg_chunk(0);
    sts_chunk(0);
    __syncthreads();

    for (int kc = 0; kc < nK; kc++) {
        const int s = kc & 1;
        if (kc + 1 < nK) ldg_chunk(kc + 1);

        // compute this chunk: 2 k-steps of 8
        #pragma unroll
        for (int ks = 0; ks < 2; ks++) {
            uint32_t af[4][4], bf[4][2];
            #pragma unroll
            for (int mi = 0; mi < 4; mi++) {
                int m0 = warp_m * 64 + mi * 16 + g;
                int kk = ks * 8 + tq;
                af[mi][0] = __float_as_uint(As[s][m0 * AS_STRIDE + kk]);
                af[mi][1] = __float_as_uint(As[s][(m0 + 8) * AS_STRIDE + kk]);
                af[mi][2] = __float_as_uint(As[s][m0 * AS_STRIDE + kk + 4]);
                af[mi][3] = __float_as_uint(As[s][(m0 + 8) * AS_STRIDE + kk + 4]);
            }
            #pragma unroll
            for (int ni = 0; ni < 4; ni++) {
                int n0 = warp_n * 32 + ni * 8 + g;
                int kk = ks * 8 + tq;
                bf[ni][0] = __float_as_uint(Bs[s][kk * BS_STRIDE + n0]);
                bf[ni][1] = __float_as_uint(Bs[s][(kk + 4) * BS_STRIDE + n0]);
            }
            #pragma unroll
            for (int mi = 0; mi < 4; mi++)
                #pragma unroll
                for (int ni = 0; ni < 4; ni++)
                    mma_tf32(acc[mi][ni], af[mi], bf[ni]);
        }

        if (kc + 1 < nK) {
            sts_chunk((kc + 1) & 1);
            __syncthreads();
        }
    }

    // Epilogue: write C (float2 per fragment row)
    #pragma unroll
    for (int mi = 0; mi < 4; mi++) {
        int row = rowBase + warp_m * 64 + mi * 16 + g;
        #pragma unroll
        for (int ni = 0; ni < 4; ni++) {
            int col = colBase + warp_n * 32 + ni * 8 + tq * 2;
            *reinterpret_cast<float2*>(&Cc[(size_t)row * Nc + col]) =
                make_float2(acc[mi][ni][0], acc[mi][ni][1]);
            *reinterpret_cast<float2*>(&Cc[(size_t)(row + 8) * Nc + col]) =
                make_float2(acc[mi][ni][2], acc[mi][ni][3]);
        }
    }
}

// ---------------------------------------------------------------------------
// Flash attention for MQA (unchanged — fp32 SIMT; round-4 target)
// ---------------------------------------------------------------------------
__global__ __launch_bounds__(256) void flash_mqa(
    const float* __restrict__ Q, const float* __restrict__ K,
    const float* __restrict__ V, float* __restrict__ Y)
{
    const int qt  = blockIdx.x;
    const int h   = blockIdx.y;
    const int b   = blockIdx.z;
    const int tid = threadIdx.x;
    const int tx  = tid & 15;
    const int ty  = tid >> 4;
    const int q0  = qt * 64;
    const float scale = 0.08838834764831845f;  // 128^-0.5

    __shared__ float sU[2 * 32 * 65];
    float (*Qs)[65]  = (float(*)[65])sU;
    float (*Ks)[65]  = (float(*)[65])(sU + 32 * 65);
    float (*Vs)[128] = (float(*)[128])sU;
    __shared__ float Ps[64][65];

    float o[4][8];
    float m[4], l[4];
    #pragma unroll
    for (int i = 0; i < 4; i++) {
        m[i] = -1e30f; l[i] = 0.0f;
        #pragma unroll
        for (int j = 0; j < 8; j++) o[i][j] = 0.0f;
    }

    const float* Qbase = Q + ((size_t)b * T_ + q0) * C_ + h * DH_;
    const float* Kbase = K + (size_t)b * T_ * DH_;
    const float* Vbase = V + (size_t)b * T_ * DH_;

    for (int s0 = 0; s0 < T_; s0 += 64) {
        float s[4][4];
        #pragma unroll
        for (int i = 0; i < 4; i++)
            #pragma unroll
            for (int j = 0; j < 4; j++) s[i][j] = 0.0f;

        for (int dk = 0; dk < DH_; dk += 32) {
            __syncthreads();
            #pragma unroll
            for (int i2 = tid; i2 < 64 * 32; i2 += 256) {
                int r = i2 >> 5, c = i2 & 31;
                Qs[c][r] = Qbase[(size_t)r * C_ + dk + c] * scale;
                Ks[c][r] = Kbase[(size_t)(s0 + r) * DH_ + dk + c];
            }
            __syncthreads();
            #pragma unroll
            for (int c = 0; c < 32; c++) {
                float ra[4], rb[4];
                #pragma unroll
                for (int i = 0; i < 4; i++) ra[i] = Qs[c][ty * 4 + i];
                #pragma unroll
                for (int j = 0; j < 4; j++) rb[j] = Ks[c][tx + 16 * j];
                #pragma unroll
                for (int i = 0; i < 4; i++)
                    #pragma unroll
                    for (int j = 0; j < 4; j++)
                        s[i][j] += ra[i] * rb[j];
            }
        }

        #pragma unroll
        for (int i = 0; i < 4; i++) {
            float mx = fmaxf(fmaxf(s[i][0], s[i][1]), fmaxf(s[i][2], s[i][3]));
            mx = fmaxf(mx, __shfl_xor_sync(0xffffffffu, mx, 8));
            mx = fmaxf(mx, __shfl_xor_sync(0xffffffffu, mx, 4));
            mx = fmaxf(mx, __shfl_xor_sync(0xffffffffu, mx, 2));
            mx = fmaxf(mx, __shfl_xor_sync(0xffffffffu, mx, 1));
            float mnew  = fmaxf(m[i], mx);
            float alpha = __expf(m[i] - mnew);
            float rs = 0.0f;
            #pragma unroll
            for (int j = 0; j < 4; j++) {
                s[i][j] = __expf(s[i][j] - mnew);
                rs += s[i][j];
            }
            rs += __shfl_xor_sync(0xffffffffu, rs, 8);
            rs += __shfl_xor_sync(0xffffffffu, rs, 4);
            rs += __shfl_xor_sync(0xffffffffu, rs, 2);
            rs += __shfl_xor_sync(0xffffffffu, rs, 1);
            l[i] = l[i] * alpha + rs;
            m[i] = mnew;
            #pragma unroll
            for (int jj = 0; jj < 8; jj++) o[i][jj] *= alpha;
        }

        #pragma unroll
        for (int i = 0; i < 4; i++)
            #pragma unroll
            for (int j = 0; j < 4; j++)
                Ps[ty * 4 + i][tx + 16 * j] = s[i][j];
        __syncthreads();

        for (int vk = 0; vk < 64; vk += 32) {
            #pragma unroll
            for (int i2 = tid; i2 < 32 * 128; i2 += 256) {
                int kr = i2 >> 7, d = i2 & 127;
                Vs[kr][d] = Vbase[(size_t)(s0 + vk + kr) * DH_ + d];
            }
            __syncthreads();
            #pragma unroll
            for (int c = 0; c < 32; c++) {
                float rp[4], rv[8];
                #pragma unroll
                for (int i = 0; i < 4; i++)  rp[i]  = Ps[ty * 4 + i][vk + c];
                #pragma unroll
                for (int jj = 0; jj < 8; jj++) rv[jj] = Vs[c][tx + 16 * jj];
                #pragma unroll
                for (int i = 0; i < 4; i++)
                    #pragma unroll
                    for (int jj = 0; jj < 8; jj++)
                        o[i][jj] += rp[i] * rv[jj];
            }
            __syncthreads();
        }
    }

    #pragma unroll
    for (int i = 0; i < 4; i++) {
        float inv = 1.0f / l[i];
        size_t row = (size_t)b * T_ + q0 + ty * 4 + i;
        #pragma unroll
        for (int jj = 0; jj < 8; jj++)
            Y[row * C_ + h * DH_ + tx + 16 * jj] = o[i][jj] * inv;
    }
}

// ---------------------------------------------------------------------------
// Launch
// ---------------------------------------------------------------------------
extern "C" void kernel_launch(void* const* d_in, const int* in_sizes, int n_in,
                              void* d_out, int out_size)
{
    const float* x  = (const float*)d_in[0];
    const float* Wq = (const float*)d_in[1];
    const float* Wk = (const float*)d_in[2];
    const float* Wv = (const float*)d_in[3];
    const float* Wo = (const float*)d_in[4];
    float* out = (float*)d_out;

    float *Qp, *Kp, *Vp, *Yp;
    cudaGetSymbolAddress((void**)&Qp, g_Q);
    cudaGetSymbolAddress((void**)&Kp, g_K);
    cudaGetSymbolAddress((void**)&Vp, g_V);
    cudaGetSymbolAddress((void**)&Yp, g_Y);

    // 1) Q = x @ Wq   [4096,2048]
    gemm_mma_tf32<<<dim3(C_ / 128, M_ / 128), 256>>>(x, Wq, Qp, M_, C_, C_);
    // 2) K = x @ Wk   [4096,128]
    gemm_mma_tf32<<<dim3(DH_ / 128, M_ / 128), 256>>>(x, Wk, Kp, M_, DH_, C_);
    // 3) V = x @ Wv
    gemm_mma_tf32<<<dim3(DH_ / 128, M_ / 128), 256>>>(x, Wv, Vp, M_, DH_, C_);
    // 4) Flash MQA attention
    flash_mqa<<<dim3(T_ / 64, H_, B_), 256>>>(Qp, Kp, Vp, Yp);
    // 5) out = Y @ Wo
    gemm_mma_tf32<<<dim3(C_ / 128, M_ / 128), 256>>>(Yp, Wo, out, M_, C_, C_);
}

// round 4
// speedup vs baseline: 3.1087x; 1.8519x over previous
#include <cuda_runtime.h>
#include <cuda_bf16.h>
#include <cstdint>

// Problem constants (fixed by setup_inputs)
#define B_   2
#define T_   2048
#define C_   2048
#define H_   16
#define DH_  128
#define M_   (B_ * T_)   // 4096

// Scratch (device globals — allocation-free per harness rules)
__device__ float g_Q[(size_t)M_ * C_];   // 32 MB
__device__ float g_K[(size_t)M_ * DH_];  //  2 MB
__device__ float g_V[(size_t)M_ * DH_];  //  2 MB
__device__ float g_Y[(size_t)M_ * C_];   // 32 MB

__device__ __forceinline__ float tf32r(float x) {
    float y;
    asm("cvt.rna.tf32.f32 %0, %1;" : "=f"(y) : "f"(x));
    return y;
}

__device__ __forceinline__ void mma_tf32(float* d, const uint32_t* a, const uint32_t* b) {
    asm volatile(
        "mma.sync.aligned.m16n8k8.row.col.f32.tf32.tf32.f32 "
        "{%0,%1,%2,%3}, {%4,%5,%6,%7}, {%8,%9}, {%0,%1,%2,%3};"
        : "+f"(d[0]), "+f"(d[1]), "+f"(d[2]), "+f"(d[3])
        : "r"(a[0]), "r"(a[1]), "r"(a[2]), "r"(a[3]), "r"(b[0]), "r"(b[1]));
}

// ---------------------------------------------------------------------------
// tf32 tensor-core GEMM via mma.sync:
//   C[Mr,Nc] = A[Mr,Kd] @ B[Kd,Nc]   (row-major, fp32 in/out)
// CTA tile 128x128, BK=16, 8 warps (2x4), warp tile 64x32.
// ---------------------------------------------------------------------------
#define AS_STRIDE 20
#define BS_STRIDE 136

__global__ __launch_bounds__(256) void gemm_mma_tf32(
    const float* __restrict__ A, const float* __restrict__ B,
    float* __restrict__ Cc, int Mr, int Nc, int Kd)
{
    __shared__ float As[2][128 * AS_STRIDE];
    __shared__ float Bs[2][16 * BS_STRIDE];

    const int tid    = threadIdx.x;
    const int wid    = tid >> 5;
    const int lane   = tid & 31;
    const int g      = lane >> 2;
    const int tq     = lane & 3;
    const int warp_m = wid & 1;
    const int warp_n = wid >> 1;
    const int rowBase = blockIdx.y * 128;
    const int colBase = blockIdx.x * 128;

    const int am = tid >> 2;
    const int aq = tid & 3;
    const int bk = tid >> 5;
    const int bn = tid & 31;

    float acc[4][4][4];
    #pragma unroll
    for (int mi = 0; mi < 4; mi++)
        #pragma unroll
        for (int ni = 0; ni < 4; ni++)
            #pragma unroll
            for (int r = 0; r < 4; r++) acc[mi][ni][r] = 0.0f;

    const int nK = Kd >> 4;

    float4 pa0, pa1, pb0, pb1;
    auto ldg_chunk = [&](int kc) {
        const float* Ab = A + (size_t)(rowBase) * Kd + kc * 16;
        const float* Bb = B + (size_t)(kc * 16) * Nc + colBase;
        pa0 = *reinterpret_cast<const float4*>(Ab + (size_t)am * Kd + aq * 4);
        pa1 = *reinterpret_cast<const float4*>(Ab + (size_t)(am + 64) * Kd + aq * 4);
        pb0 = *reinterpret_cast<const float4*>(Bb + (size_t)bk * Nc + bn * 4);
        pb1 = *reinterpret_cast<const float4*>(Bb + (size_t)(bk + 8) * Nc + bn * 4);
    };
    auto sts_chunk = [&](int s) {
        float4 va0 = make_float4(tf32r(pa0.x), tf32r(pa0.y), tf32r(pa0.z), tf32r(pa0.w));
        float4 va1 = make_float4(tf32r(pa1.x), tf32r(pa1.y), tf32r(pa1.z), tf32r(pa1.w));
        float4 vb0 = make_float4(tf32r(pb0.x), tf32r(pb0.y), tf32r(pb0.z), tf32r(pb0.w));
        float4 vb1 = make_float4(tf32r(pb1.x), tf32r(pb1.y), tf32r(pb1.z), tf32r(pb1.w));
        *reinterpret_cast<float4*>(&As[s][am * AS_STRIDE + aq * 4])        = va0;
        *reinterpret_cast<float4*>(&As[s][(am + 64) * AS_STRIDE + aq * 4]) = va1;
        *reinterpret_cast<float4*>(&Bs[s][bk * BS_STRIDE + bn * 4])        = vb0;
        *reinterpret_cast<float4*>(&Bs[s][(bk + 8) * BS_STRIDE + bn * 4])  = vb1;
    };

    ldg_chunk(0);
    sts_chunk(0);
    __syncthreads();

    for (int kc = 0; kc < nK; kc++) {
        const int s = kc & 1;
        if (kc + 1 < nK) ldg_chunk(kc + 1);

        #pragma unroll
        for (int ks = 0; ks < 2; ks++) {
            uint32_t af[4][4], bf[4][2];
            #pragma unroll
            for (int mi = 0; mi < 4; mi++) {
                int m0 = warp_m * 64 + mi * 16 + g;
                int kk = ks * 8 + tq;
                af[mi][0] = __float_as_uint(As[s][m0 * AS_STRIDE + kk]);
                af[mi][1] = __float_as_uint(As[s][(m0 + 8) * AS_STRIDE + kk]);
                af[mi][2] = __float_as_uint(As[s][m0 * AS_STRIDE + kk + 4]);
                af[mi][3] = __float_as_uint(As[s][(m0 + 8) * AS_STRIDE + kk + 4]);
            }
            #pragma unroll
            for (int ni = 0; ni < 4; ni++) {
                int n0 = warp_n * 32 + ni * 8 + g;
                int kk = ks * 8 + tq;
                bf[ni][0] = __float_as_uint(Bs[s][kk * BS_STRIDE + n0]);
                bf[ni][1] = __float_as_uint(Bs[s][(kk + 4) * BS_STRIDE + n0]);
            }
            #pragma unroll
            for (int mi = 0; mi < 4; mi++)
                #pragma unroll
                for (int ni = 0; ni < 4; ni++)
                    mma_tf32(acc[mi][ni], af[mi], bf[ni]);
        }

        if (kc + 1 < nK) {
            sts_chunk((kc + 1) & 1);
            __syncthreads();
        }
    }

    #pragma unroll
    for (int mi = 0; mi < 4; mi++) {
        int row = rowBase + warp_m * 64 + mi * 16 + g;
        #pragma unroll
        for (int ni = 0; ni < 4; ni++) {
            int col = colBase + warp_n * 32 + ni * 8 + tq * 2;
            *reinterpret_cast<float2*>(&Cc[(size_t)row * Nc + col]) =
                make_float2(acc[mi][ni][0], acc[mi][ni][1]);
            *reinterpret_cast<float2*>(&Cc[(size_t)(row + 8) * Nc + col]) =
                make_float2(acc[mi][ni][2], acc[mi][ni][3]);
        }
    }
}

// ---------------------------------------------------------------------------
// Tensor-core flash attention for MQA (tf32 mma.sync).
// CTA: 128 queries x 1 head; 8 warps, 16 query rows each.
// Key tiles of 64; K/V in natural [key][d] smem layout (stride 132);
// P routed through per-warp smem (stride 68). Online softmax on C-fragments.
// Grid: (T/128, H, B). 256 threads. Dynamic smem 100 KB.
// ---------------------------------------------------------------------------
#define KV_STR 132
#define P_STR  68
#define FL_SMEM ((2 * 64 * KV_STR + 8 * 16 * P_STR) * 4)   // 102400 B

__global__ __launch_bounds__(256, 1) void flash_mqa_mma(
    const float* __restrict__ Q, const float* __restrict__ K,
    const float* __restrict__ V, float* __restrict__ Y)
{
    extern __shared__ float fsm[];
    float* Ks = fsm;                     // [64][132]
    float* Vs = fsm + 64 * KV_STR;       // [64][132]
    float* Ps = fsm + 2 * 64 * KV_STR;   // 8 x [16][68]

    const int tid  = threadIdx.x;
    const int wid  = tid >> 5;
    const int lane = tid & 31;
    const int g    = lane >> 2;
    const int tq   = lane & 3;
    const int qt   = blockIdx.x;
    const int h    = blockIdx.y;
    const int b    = blockIdx.z;
    const int q0   = qt * 128;
    const int m0   = wid * 16;
    const float scale = 0.08838834764831845f;  // 128^-0.5

    // ---- Stage Q (scaled, tf32) into the Ks+Vs region (128x132 floats), grab frags
    const float* Qb = Q + ((size_t)b * T_ + q0) * C_ + h * DH_;
    #pragma unroll
    for (int i = tid; i < 128 * 32; i += 256) {
        int r = i >> 5, c4 = i & 31;
        float4 v = *reinterpret_cast<const float4*>(Qb + (size_t)r * C_ + c4 * 4);
        v.x = tf32r(v.x * scale); v.y = tf32r(v.y * scale);
        v.z = tf32r(v.z * scale); v.w = tf32r(v.w * scale);
        *reinterpret_cast<float4*>(&fsm[r * KV_STR + c4 * 4]) = v;
    }
    __syncthreads();

    uint32_t qf[16][4];
    #pragma unroll
    for (int kk = 0; kk < 16; kk++) {
        qf[kk][0] = __float_as_uint(fsm[(m0 + g)     * KV_STR + 8 * kk + tq]);
        qf[kk][1] = __float_as_uint(fsm[(m0 + g + 8) * KV_STR + 8 * kk + tq]);
        qf[kk][2] = __float_as_uint(fsm[(m0 + g)     * KV_STR + 8 * kk + tq + 4]);
        qf[kk][3] = __float_as_uint(fsm[(m0 + g + 8) * KV_STR + 8 * kk + tq + 4]);
    }
    __syncthreads();

    float oacc[16][4];
    #pragma unroll
    for (int nf = 0; nf < 16; nf++)
        #pragma unroll
        for (int r = 0; r < 4; r++) oacc[nf][r] = 0.0f;
    float mrow0 = -1e30f, mrow1 = -1e30f, lrow0 = 0.0f, lrow1 = 0.0f;

    const float* Kb = K + (size_t)b * T_ * DH_;
    const float* Vb = V + (size_t)b * T_ * DH_;
    float* Psw = Ps + wid * 16 * P_STR;

    for (int s0 = 0; s0 < T_; s0 += 64) {
        // ---- load K,V tiles (64x128 each), tf32-rounded
        #pragma unroll
        for (int i = tid; i < 64 * 32; i += 256) {
            int r = i >> 5, c4 = i & 31;
            float4 kv = *reinterpret_cast<const float4*>(Kb + (size_t)(s0 + r) * DH_ + c4 * 4);
            kv.x = tf32r(kv.x); kv.y = tf32r(kv.y); kv.z = tf32r(kv.z); kv.w = tf32r(kv.w);
            *reinterpret_cast<float4*>(&Ks[r * KV_STR + c4 * 4]) = kv;
            float4 vv = *reinterpret_cast<const float4*>(Vb + (size_t)(s0 + r) * DH_ + c4 * 4);
            vv.x = tf32r(vv.x); vv.y = tf32r(vv.y); vv.z = tf32r(vv.z); vv.w = tf32r(vv.w);
            *reinterpret_cast<float4*>(&Vs[r * KV_STR + c4 * 4]) = vv;
        }
        __syncthreads();

        // ---- S = Q @ K^T  (warp: 16 rows x 64 keys)
        float sacc[8][4];
        #pragma unroll
        for (int nf = 0; nf < 8; nf++)
            #pragma unroll
            for (int r = 0; r < 4; r++) sacc[nf][r] = 0.0f;

        #pragma unroll
        for (int kk = 0; kk < 16; kk++) {
            #pragma unroll
            for (int nf = 0; nf < 8; nf++) {
                uint32_t bfr[2];
                bfr[0] = __float_as_uint(Ks[(nf * 8 + g) * KV_STR + 8 * kk + tq]);
                bfr[1] = __float_as_uint(Ks[(nf * 8 + g) * KV_STR + 8 * kk + tq + 4]);
                mma_tf32(sacc[nf], qf[kk], bfr);
            }
        }

        // ---- online softmax (rows m0+g and m0+g+8)
        float mx0 = -1e30f, mx1 = -1e30f;
        #pragma unroll
        for (int nf = 0; nf < 8; nf++) {
            mx0 = fmaxf(mx0, fmaxf(sacc[nf][0], sacc[nf][1]));
            mx1 = fmaxf(mx1, fmaxf(sacc[nf][2], sacc[nf][3]));
        }
        mx0 = fmaxf(mx0, __shfl_xor_sync(0xffffffffu, mx0, 1));
        mx0 = fmaxf(mx0, __shfl_xor_sync(0xffffffffu, mx0, 2));
        mx1 = fmaxf(mx1, __shfl_xor_sync(0xffffffffu, mx1, 1));
        mx1 = fmaxf(mx1, __shfl_xor_sync(0xffffffffu, mx1, 2));
        float mn0 = fmaxf(mrow0, mx0), mn1 = fmaxf(mrow1, mx1);
        float a0 = __expf(mrow0 - mn0), a1 = __expf(mrow1 - mn1);
        float rs0 = 0.0f, rs1 = 0.0f;
        #pragma unroll
        for (int nf = 0; nf < 8; nf++) {
            sacc[nf][0] = __expf(sacc[nf][0] - mn0);
            sacc[nf][1] = __expf(sacc[nf][1] - mn0);
            sacc[nf][2] = __expf(sacc[nf][2] - mn1);
            sacc[nf][3] = __expf(sacc[nf][3] - mn1);
            rs0 += sacc[nf][0] + sacc[nf][1];
            rs1 += sacc[nf][2] + sacc[nf][3];
        }
        rs0 += __shfl_xor_sync(0xffffffffu, rs0, 1);
        rs0 += __shfl_xor_sync(0xffffffffu, rs0, 2);
        rs1 += __shfl_xor_sync(0xffffffffu, rs1, 1);
        rs1 += __shfl_xor_sync(0xffffffffu, rs1, 2);
        lrow0 = lrow0 * a0 + rs0;  mrow0 = mn0;
        lrow1 = lrow1 * a1 + rs1;  mrow1 = mn1;
        #pragma unroll
        for (int nf = 0; nf < 16; nf++) {
            oacc[nf][0] *= a0; oacc[nf][1] *= a0;
            oacc[nf][2] *= a1; oacc[nf][3] *= a1;
        }
        // publish P (tf32-rounded) to per-warp smem
        #pragma unroll
        for (int nf = 0; nf < 8; nf++) {
            *reinterpret_cast<float2*>(&Psw[g * P_STR + nf * 8 + tq * 2]) =
                make_float2(tf32r(sacc[nf][0]), tf32r(sacc[nf][1]));
            *reinterpret_cast<float2*>(&Psw[(g + 8) * P_STR + nf * 8 + tq * 2]) =
                make_float2(tf32r(sacc[nf][2]), tf32r(sacc[nf][3]));
        }
        __syncwarp();

        // ---- O += P @ V   (warp: 16 rows x 128 d, k = 64 keys)
        #pragma unroll
        for (int kk = 0; kk < 8; kk++) {
            uint32_t pf[4];
            pf[0] = __float_as_uint(Psw[g       * P_STR + 8 * kk + tq]);
            pf[1] = __float_as_uint(Psw[(g + 8) * P_STR + 8 * kk + tq]);
            pf[2] = __float_as_uint(Psw[g       * P_STR + 8 * kk + tq + 4]);
            pf[3] = __float_as_uint(Psw[(g + 8) * P_STR + 8 * kk + tq + 4]);
            #pragma unroll
            for (int nf = 0; nf < 16; nf++) {
                uint32_t bfr[2];
                bfr[0] = __float_as_uint(Vs[(8 * kk + tq)     * KV_STR + nf * 8 + g]);
                bfr[1] = __float_as_uint(Vs[(8 * kk + tq + 4) * KV_STR + nf * 8 + g]);
                mma_tf32(oacc[nf], pf, bfr);
            }
        }
        __syncthreads();
    }

    // ---- epilogue: normalize, write Y[b*T+q][h*128+d]
    float i0 = 1.0f / lrow0, i1 = 1.0f / lrow1;
    size_t row0 = (size_t)b * T_ + q0 + m0 + g;
    size_t row1 = row0 + 8;
    #pragma unroll
    for (int nf = 0; nf < 16; nf++) {
        int col = h * DH_ + nf * 8 + tq * 2;
        *reinterpret_cast<float2*>(&Y[row0 * C_ + col]) =
            make_float2(oacc[nf][0] * i0, oacc[nf][1] * i0);
        *reinterpret_cast<float2*>(&Y[row1 * C_ + col]) =
            make_float2(oacc[nf][2] * i1, oacc[nf][3] * i1);
    }
}

// ---------------------------------------------------------------------------
// Launch
// ---------------------------------------------------------------------------
extern "C" void kernel_launch(void* const* d_in, const int* in_sizes, int n_in,
                              void* d_out, int out_size)
{
    const float* x  = (const float*)d_in[0];
    const float* Wq = (const float*)d_in[1];
    const float* Wk = (const float*)d_in[2];
    const float* Wv = (const float*)d_in[3];
    const float* Wo = (const float*)d_in[4];
    float* out = (float*)d_out;

    float *Qp, *Kp, *Vp, *Yp;
    cudaGetSymbolAddress((void**)&Qp, g_Q);
    cudaGetSymbolAddress((void**)&Kp, g_K);
    cudaGetSymbolAddress((void**)&Vp, g_V);
    cudaGetSymbolAddress((void**)&Yp, g_Y);

    cudaFuncSetAttribute(flash_mqa_mma, cudaFuncAttributeMaxDynamicSharedMemorySize, FL_SMEM);

    // 1) Q = x @ Wq
    gemm_mma_tf32<<<dim3(C_ / 128, M_ / 128), 256>>>(x, Wq, Qp, M_, C_, C_);
    // 2) K = x @ Wk
    gemm_mma_tf32<<<dim3(DH_ / 128, M_ / 128), 256>>>(x, Wk, Kp, M_, DH_, C_);
    // 3) V = x @ Wv
    gemm_mma_tf32<<<dim3(DH_ / 128, M_ / 128), 256>>>(x, Wv, Vp, M_, DH_, C_);
    // 4) Flash MQA attention (tensor cores)
    flash_mqa_mma<<<dim3(T_ / 128, H_, B_), 256, FL_SMEM>>>(Qp, Kp, Vp, Yp);
    // 5) out = Y @ Wo
    gemm_mma_tf32<<<dim3(C_ / 128, M_ / 128), 256>>>(Yp, Wo, out, M_, C_, C_);
}

// round 5
// speedup vs baseline: 3.8677x; 1.2441x over previous
#include <cuda_runtime.h>
#include <cstdint>

// Problem constants
#define B_   2
#define T_   2048
#define C_   2048
#define H_   16
#define DH_  128
#define M_   (B_ * T_)   // 4096

// Scratch (device globals — allocation-free per harness rules)
__device__ float g_Q[(size_t)M_ * C_];     // 32 MB (tf32-rounded)
__device__ float g_K[(size_t)M_ * DH_];    //  2 MB (tf32-rounded)
__device__ float g_V[(size_t)M_ * DH_];    //  2 MB (tf32-rounded)
__device__ float g_Y[(size_t)M_ * C_];     // 32 MB (tf32-rounded)
__device__ float g_Xr[(size_t)M_ * C_];    // 32 MB x rounded
__device__ float g_Wqr[(size_t)C_ * C_];   // 16 MB
__device__ float g_Wkr[(size_t)C_ * DH_];  //  1 MB
__device__ float g_Wvr[(size_t)C_ * DH_];  //  1 MB
__device__ float g_Wor[(size_t)C_ * C_];   // 16 MB

__device__ __forceinline__ float tf32r(float x) {
    float y;
    asm("cvt.rna.tf32.f32 %0, %1;" : "=f"(y) : "f"(x));
    return y;
}

__device__ __forceinline__ uint32_t smem_u32(const void* p) {
    uint32_t a;
    asm("{ .reg .u64 t; cvta.to.shared.u64 t, %1; cvt.u32.u64 %0, t; }"
        : "=r"(a) : "l"(p));
    return a;
}

__device__ __forceinline__ void cp16(uint32_t dst, const void* src) {
    asm volatile("cp.async.cg.shared.global [%0], [%1], 16;" :: "r"(dst), "l"(src));
}
#define CP_COMMIT() asm volatile("cp.async.commit_group;" ::: "memory")
#define CP_WAIT(n)  asm volatile("cp.async.wait_group %0;" :: "n"(n) : "memory")

__device__ __forceinline__ void mma_tf32(float* d, const uint32_t* a, const uint32_t* b) {
    asm volatile(
        "mma.sync.aligned.m16n8k8.row.col.f32.tf32.tf32.f32 "
        "{%0,%1,%2,%3}, {%4,%5,%6,%7}, {%8,%9}, {%0,%1,%2,%3};"
        : "+f"(d[0]), "+f"(d[1]), "+f"(d[2]), "+f"(d[3])
        : "r"(a[0]), "r"(a[1]), "r"(a[2]), "r"(a[3]), "r"(b[0]), "r"(b[1]));
}

// ---------------------------------------------------------------------------
// Pre-round: out[i] = tf32(in[i])   (vectorized)
// ---------------------------------------------------------------------------
__global__ __launch_bounds__(256) void round_tf32(
    const float4* __restrict__ in, float4* __restrict__ out, int n4)
{
    int i = blockIdx.x * 256 + threadIdx.x;
    if (i < n4) {
        float4 v = in[i];
        v.x = tf32r(v.x); v.y = tf32r(v.y); v.z = tf32r(v.z); v.w = tf32r(v.w);
        out[i] = v;
    }
}

// ---------------------------------------------------------------------------
// tf32 GEMM (inputs pre-rounded): C[.,Nc] = A @ B, cp.async double-buffered.
// CTA tile 128x128, BK=16, 8 warps (2x4), warp tile 64x32, occupancy 2.
// ---------------------------------------------------------------------------
#define AS_STRIDE 20
#define BS_STRIDE 136

template<bool ROUND_OUT>
__device__ __forceinline__ void gemm_body(
    const float* __restrict__ A, const float* __restrict__ B,
    float* __restrict__ Cc, int Nc, int Kd)
{
    __shared__ float As[2][128 * AS_STRIDE];  // 20.0 KB
    __shared__ float Bs[2][16 * BS_STRIDE];   // 17.0 KB

    const int tid    = threadIdx.x;
    const int wid    = tid >> 5;
    const int lane   = tid & 31;
    const int g      = lane >> 2;
    const int tq     = lane & 3;
    const int warp_m = wid & 1;
    const int warp_n = wid >> 1;
    const int rowBase = blockIdx.y * 128;
    const int colBase = blockIdx.x * 128;

    const uint32_t asb[2] = { smem_u32(As[0]), smem_u32(As[1]) };
    const uint32_t bsb[2] = { smem_u32(Bs[0]), smem_u32(Bs[1]) };

    float acc[4][4][4];
    #pragma unroll
    for (int mi = 0; mi < 4; mi++)
        #pragma unroll
        for (int ni = 0; ni < 4; ni++)
            #pragma unroll
            for (int r = 0; r < 4; r++) acc[mi][ni][r] = 0.0f;

    const int nK = Kd >> 4;

    auto issue = [&](int kc, int s) {
        // A tile: 128 rows x 16 floats = 512 x 16B
        #pragma unroll
        for (int j = 0; j < 2; j++) {
            int op = tid + 256 * j;
            int r = op >> 2, sg = op & 3;
            cp16(asb[s] + (uint32_t)(r * AS_STRIDE + sg * 4) * 4,
                 A + (size_t)(rowBase + r) * Kd + kc * 16 + sg * 4);
        }
        // B tile: 16 rows x 128 floats = 512 x 16B
        #pragma unroll
        for (int j = 0; j < 2; j++) {
            int op = tid + 256 * j;
            int r = op >> 5, sg = op & 31;
            cp16(bsb[s] + (uint32_t)(r * BS_STRIDE + sg * 4) * 4,
                 B + (size_t)(kc * 16 + r) * Nc + colBase + sg * 4);
        }
    };

    issue(0, 0);
    CP_COMMIT();

    for (int kc = 0; kc < nK; kc++) {
        const int s = kc & 1;
        if (kc + 1 < nK) {
            issue(kc + 1, s ^ 1);
            CP_COMMIT();
            CP_WAIT(1);
        } else {
            CP_WAIT(0);
        }
        __syncthreads();

        #pragma unroll
        for (int ks = 0; ks < 2; ks++) {
            uint32_t af[4][4], bf[4][2];
            #pragma unroll
            for (int mi = 0; mi < 4; mi++) {
                int m0 = warp_m * 64 + mi * 16 + g;
                int kk = ks * 8 + tq;
                af[mi][0] = __float_as_uint(As[s][m0 * AS_STRIDE + kk]);
                af[mi][1] = __float_as_uint(As[s][(m0 + 8) * AS_STRIDE + kk]);
                af[mi][2] = __float_as_uint(As[s][m0 * AS_STRIDE + kk + 4]);
                af[mi][3] = __float_as_uint(As[s][(m0 + 8) * AS_STRIDE + kk + 4]);
            }
            #pragma unroll
            for (int ni = 0; ni < 4; ni++) {
                int n0 = warp_n * 32 + ni * 8 + g;
                int kk = ks * 8 + tq;
                bf[ni][0] = __float_as_uint(Bs[s][kk * BS_STRIDE + n0]);
                bf[ni][1] = __float_as_uint(Bs[s][(kk + 4) * BS_STRIDE + n0]);
            }
            #pragma unroll
            for (int mi = 0; mi < 4; mi++)
                #pragma unroll
                for (int ni = 0; ni < 4; ni++)
                    mma_tf32(acc[mi][ni], af[mi], bf[ni]);
        }
        __syncthreads();
    }

    #pragma unroll
    for (int mi = 0; mi < 4; mi++) {
        int row = rowBase + warp_m * 64 + mi * 16 + g;
        #pragma unroll
        for (int ni = 0; ni < 4; ni++) {
            int col = colBase + warp_n * 32 + ni * 8 + tq * 2;
            float v0 = acc[mi][ni][0], v1 = acc[mi][ni][1];
            float v2 = acc[mi][ni][2], v3 = acc[mi][ni][3];
            if (ROUND_OUT) { v0 = tf32r(v0); v1 = tf32r(v1); v2 = tf32r(v2); v3 = tf32r(v3); }
            *reinterpret_cast<float2*>(&Cc[(size_t)row * Nc + col])       = make_float2(v0, v1);
            *reinterpret_cast<float2*>(&Cc[(size_t)(row + 8) * Nc + col]) = make_float2(v2, v3);
        }
    }
}

template<bool ROUND_OUT>
__global__ __launch_bounds__(256, 2) void gemm_async(
    const float* __restrict__ A, const float* __restrict__ B,
    float* __restrict__ Cc, int Nc, int Kd)
{
    gemm_body<ROUND_OUT>(A, B, Cc, Nc, Kd);
}

// Fused K/V projections (blockIdx.z selects weight/output)
__global__ __launch_bounds__(256, 2) void gemm_kv(
    const float* __restrict__ A,
    const float* __restrict__ Bk, const float* __restrict__ Bv,
    float* __restrict__ Ck, float* __restrict__ Cv, int Nc, int Kd)
{
    const float* Bp = blockIdx.z ? Bv : Bk;
    float*       Cp = blockIdx.z ? Cv : Ck;
    gemm_body<true>(A, Bp, Cp, Nc, Kd);
}

// ---------------------------------------------------------------------------
// Tensor-core flash attention for MQA (tf32, cp.async double-buffered K/V).
// CTA: 128 queries x 1 head; 8 warps x 16 rows. Key tiles of 64.
// Ks stride 132 (bank 4g+tq), Vs stride 136 (bank 8tq+g) — both conflict-free.
// Inputs Q/K/V are pre-rounded tf32; scale applied post-MMA; Y written rounded.
// ---------------------------------------------------------------------------
#define KSTR 132
#define VSTR 136
#define PSTR 68
#define OFF_K(s) ((s) * 64 * KSTR)                    // 0, 8448
#define OFF_V(s) (2 * 64 * KSTR + (s) * 64 * VSTR)    // 16896, 25600
#define OFF_P    (2 * 64 * KSTR + 2 * 64 * VSTR)      // 34304
#define FL_SMEM  ((OFF_P + 8 * 16 * PSTR) * 4)        // 172032 B

__global__ __launch_bounds__(256, 1) void flash_mqa_mma(
    const float* __restrict__ Q, const float* __restrict__ K,
    const float* __restrict__ V, float* __restrict__ Y)
{
    extern __shared__ float fsm[];
    const uint32_t sb = smem_u32(fsm);

    const int tid  = threadIdx.x;
    const int wid  = tid >> 5;
    const int lane = tid & 31;
    const int g    = lane >> 2;
    const int tq   = lane & 3;
    const int q0   = blockIdx.x * 128;
    const int h    = blockIdx.y;
    const int b    = blockIdx.z;
    const int m0   = wid * 16;
    const float scale = 0.08838834764831845f;  // 128^-0.5

    // ---- Stage Q (128x128, stride 132) via cp.async, grab fragments
    const float* Qb = Q + ((size_t)b * T_ + q0) * C_ + h * DH_;
    #pragma unroll
    for (int j = 0; j < 16; j++) {
        int op = tid + 256 * j;           // 0..4095
        int r = op >> 5, sg = op & 31;
        cp16(sb + (uint32_t)(r * KSTR + sg * 4) * 4, Qb + (size_t)r * C_ + sg * 4);
    }
    CP_COMMIT(); CP_WAIT(0);
    __syncthreads();

    uint32_t qf[16][4];
    #pragma unroll
    for (int kk = 0; kk < 16; kk++) {
        qf[kk][0] = __float_as_uint(fsm[(m0 + g)     * KSTR + 8 * kk + tq]);
        qf[kk][1] = __float_as_uint(fsm[(m0 + g + 8) * KSTR + 8 * kk + tq]);
        qf[kk][2] = __float_as_uint(fsm[(m0 + g)     * KSTR + 8 * kk + tq + 4]);
        qf[kk][3] = __float_as_uint(fsm[(m0 + g + 8) * KSTR + 8 * kk + tq + 4]);
    }
    __syncthreads();

    float oacc[16][4];
    #pragma unroll
    for (int nf = 0; nf < 16; nf++)
        #pragma unroll
        for (int r = 0; r < 4; r++) oacc[nf][r] = 0.0f;
    float mrow0 = -1e30f, mrow1 = -1e30f, lrow0 = 0.0f, lrow1 = 0.0f;

    const float* Kb = K + (size_t)b * T_ * DH_;
    const float* Vb = V + (size_t)b * T_ * DH_;
    float* Psw = fsm + OFF_P + wid * 16 * PSTR;

    auto issue_kv = [&](int s0t, int s) {
        const float* Kt = Kb + (size_t)s0t * DH_;
        const float* Vt = Vb + (size_t)s0t * DH_;
        #pragma unroll
        for (int j = 0; j < 8; j++) {
            int op = tid + 256 * j;       // 0..2047
            int r = op >> 5, sg = op & 31;
            cp16(sb + (uint32_t)(OFF_K(s) + r * KSTR + sg * 4) * 4,
                 Kt + (size_t)r * DH_ + sg * 4);
        }
        #pragma unroll
        for (int j = 0; j < 8; j++) {
            int op = tid + 256 * j;
            int r = op >> 5, sg = op & 31;
            cp16(sb + (uint32_t)(OFF_V(s) + r * VSTR + sg * 4) * 4,
                 Vt + (size_t)r * DH_ + sg * 4);
        }
    };

    issue_kv(0, 0);
    CP_COMMIT();

    const int nTiles = T_ / 64;  // 32
    for (int it = 0; it < nTiles; it++) {
        const int s = it & 1;
        if (it + 1 < nTiles) {
            issue_kv((it + 1) * 64, s ^ 1);
            CP_COMMIT();
            CP_WAIT(1);
        } else {
            CP_WAIT(0);
        }
        __syncthreads();

        const float* Ks = fsm + OFF_K(s);
        const float* Vs = fsm + OFF_V(s);

        // ---- S = Q @ K^T  (16 rows x 64 keys per warp)
        float sacc[8][4];
        #pragma unroll
        for (int nf = 0; nf < 8; nf++)
            #pragma unroll
            for (int r = 0; r < 4; r++) sacc[nf][r] = 0.0f;

        #pragma unroll
        for (int kk = 0; kk < 16; kk++) {
            #pragma unroll
            for (int nf = 0; nf < 8; nf++) {
                uint32_t bfr[2];
                bfr[0] = __float_as_uint(Ks[(nf * 8 + g) * KSTR + 8 * kk + tq]);
                bfr[1] = __float_as_uint(Ks[(nf * 8 + g) * KSTR + 8 * kk + tq + 4]);
                mma_tf32(sacc[nf], qf[kk], bfr);
            }
        }
        // apply softmax scale post-MMA
        #pragma unroll
        for (int nf = 0; nf < 8; nf++) {
            sacc[nf][0] *= scale; sacc[nf][1] *= scale;
            sacc[nf][2] *= scale; sacc[nf][3] *= scale;
        }

        // ---- online softmax (rows m0+g, m0+g+8)
        float mx0 = -1e30f, mx1 = -1e30f;
        #pragma unroll
        for (int nf = 0; nf < 8; nf++) {
            mx0 = fmaxf(mx0, fmaxf(sacc[nf][0], sacc[nf][1]));
            mx1 = fmaxf(mx1, fmaxf(sacc[nf][2], sacc[nf][3]));
        }
        mx0 = fmaxf(mx0, __shfl_xor_sync(0xffffffffu, mx0, 1));
        mx0 = fmaxf(mx0, __shfl_xor_sync(0xffffffffu, mx0, 2));
        mx1 = fmaxf(mx1, __shfl_xor_sync(0xffffffffu, mx1, 1));
        mx1 = fmaxf(mx1, __shfl_xor_sync(0xffffffffu, mx1, 2));
        float mn0 = fmaxf(mrow0, mx0), mn1 = fmaxf(mrow1, mx1);
        float a0 = __expf(mrow0 - mn0), a1 = __expf(mrow1 - mn1);
        float rs0 = 0.0f, rs1 = 0.0f;
        #pragma unroll
        for (int nf = 0; nf < 8; nf++) {
            sacc[nf][0] = __expf(sacc[nf][0] - mn0);
            sacc[nf][1] = __expf(sacc[nf][1] - mn0);
            sacc[nf][2] = __expf(sacc[nf][2] - mn1);
            sacc[nf][3] = __expf(sacc[nf][3] - mn1);
            rs0 += sacc[nf][0] + sacc[nf][1];
            rs1 += sacc[nf][2] + sacc[nf][3];
        }
        rs0 += __shfl_xor_sync(0xffffffffu, rs0, 1);
        rs0 += __shfl_xor_sync(0xffffffffu, rs0, 2);
        rs1 += __shfl_xor_sync(0xffffffffu, rs1, 1);
        rs1 += __shfl_xor_sync(0xffffffffu, rs1, 2);
        lrow0 = lrow0 * a0 + rs0;  mrow0 = mn0;
        lrow1 = lrow1 * a1 + rs1;  mrow1 = mn1;
        #pragma unroll
        for (int nf = 0; nf < 16; nf++) {
            oacc[nf][0] *= a0; oacc[nf][1] *= a0;
            oacc[nf][2] *= a1; oacc[nf][3] *= a1;
        }

        // publish P (tf32) to per-warp smem
        #pragma unroll
        for (int nf = 0; nf < 8; nf++) {
            *reinterpret_cast<float2*>(&Psw[g * PSTR + nf * 8 + tq * 2]) =
                make_float2(tf32r(sacc[nf][0]), tf32r(sacc[nf][1]));
            *reinterpret_cast<float2*>(&Psw[(g + 8) * PSTR + nf * 8 + tq * 2]) =
                make_float2(tf32r(sacc[nf][2]), tf32r(sacc[nf][3]));
        }
        __syncwarp();

        // ---- O += P @ V
        #pragma unroll
        for (int kk = 0; kk < 8; kk++) {
            uint32_t pf[4];
            pf[0] = __float_as_uint(Psw[g       * PSTR + 8 * kk + tq]);
            pf[1] = __float_as_uint(Psw[(g + 8) * PSTR + 8 * kk + tq]);
            pf[2] = __float_as_uint(Psw[g       * PSTR + 8 * kk + tq + 4]);
            pf[3] = __float_as_uint(Psw[(g + 8) * PSTR + 8 * kk + tq + 4]);
            #pragma unroll
            for (int nf = 0; nf < 16; nf++) {
                uint32_t bfr[2];
                bfr[0] = __float_as_uint(Vs[(8 * kk + tq)     * VSTR + nf * 8 + g]);
                bfr[1] = __float_as_uint(Vs[(8 * kk + tq + 4) * VSTR + nf * 8 + g]);
                mma_tf32(oacc[nf], pf, bfr);
            }
        }
        __syncthreads();
    }

    // ---- epilogue: normalize, round to tf32 (feeds O-proj), write Y
    float i0 = 1.0f / lrow0, i1 = 1.0f / lrow1;
    size_t row0 = (size_t)b * T_ + q0 + m0 + g;
    size_t row1 = row0 + 8;
    #pragma unroll
    for (int nf = 0; nf < 16; nf++) {
        int col = h * DH_ + nf * 8 + tq * 2;
        *reinterpret_cast<float2*>(&Y[row0 * C_ + col]) =
            make_float2(tf32r(oacc[nf][0] * i0), tf32r(oacc[nf][1] * i0));
        *reinterpret_cast<float2*>(&Y[row1 * C_ + col]) =
            make_float2(tf32r(oacc[nf][2] * i1), tf32r(oacc[nf][3] * i1));
    }
}

// ---------------------------------------------------------------------------
// Launch
// ---------------------------------------------------------------------------
extern "C" void kernel_launch(void* const* d_in, const int* in_sizes, int n_in,
                              void* d_out, int out_size)
{
    const float* x  = (const float*)d_in[0];
    const float* Wq = (const float*)d_in[1];
    const float* Wk = (const float*)d_in[2];
    const float* Wv = (const float*)d_in[3];
    const float* Wo = (const float*)d_in[4];
    float* out = (float*)d_out;

    float *Qp, *Kp, *Vp, *Yp, *Xr, *Wqr, *Wkr, *Wvr, *Wor;
    cudaGetSymbolAddress((void**)&Qp,  g_Q);
    cudaGetSymbolAddress((void**)&Kp,  g_K);
    cudaGetSymbolAddress((void**)&Vp,  g_V);
    cudaGetSymbolAddress((void**)&Yp,  g_Y);
    cudaGetSymbolAddress((void**)&Xr,  g_Xr);
    cudaGetSymbolAddress((void**)&Wqr, g_Wqr);
    cudaGetSymbolAddress((void**)&Wkr, g_Wkr);
    cudaGetSymbolAddress((void**)&Wvr, g_Wvr);
    cudaGetSymbolAddress((void**)&Wor, g_Wor);

    cudaFuncSetAttribute(flash_mqa_mma, cudaFuncAttributeMaxDynamicSharedMemorySize, FL_SMEM);

    // Pre-round inputs to tf32 (once)
    round_tf32<<<(M_ * C_ / 4) / 256, 256>>>((const float4*)x,  (float4*)Xr,  M_ * C_ / 4);
    round_tf32<<<(C_ * C_ / 4) / 256, 256>>>((const float4*)Wq, (float4*)Wqr, C_ * C_ / 4);
    round_tf32<<<(C_ * DH_ / 4) / 256, 256>>>((const float4*)Wk, (float4*)Wkr, C_ * DH_ / 4);
    round_tf32<<<(C_ * DH_ / 4) / 256, 256>>>((const float4*)Wv, (float4*)Wvr, C_ * DH_ / 4);
    round_tf32<<<(C_ * C_ / 4) / 256, 256>>>((const float4*)Wo, (float4*)Wor, C_ * C_ / 4);

    // 1) Q = xr @ Wqr (rounded output)
    gemm_async<true><<<dim3(C_ / 128, M_ / 128), 256>>>(Xr, Wqr, Qp, C_, C_);
    // 2+3) K,V projections fused (rounded outputs)
    gemm_kv<<<dim3(1, M_ / 128, 2), 256>>>(Xr, Wkr, Wvr, Kp, Vp, DH_, C_);
    // 4) Flash MQA attention (rounded Y output)
    flash_mqa_mma<<<dim3(T_ / 128, H_, B_), 256, FL_SMEM>>>(Qp, Kp, Vp, Yp);
    // 5) out = Y @ Wor (full-precision output)
    gemm_async<false><<<dim3(C_ / 128, M_ / 128), 256>>>(Yp, Wor, out, C_, C_);
}